// round 2
// baseline (speedup 1.0000x reference)
#include <cuda_runtime.h>

// Problem shape (fixed by setup_inputs): B=8192 rows, D=256 dim.
#define B 8192
#define D 256
#define INV_T 5.0f   // 1 / TEMPERATURE(0.2)

// Scratch (allocations are forbidden; __device__ globals are the sanctioned path)
__device__ float g_un[B * D];   // normalized user embeddings
__device__ float g_pn[B * D];   // normalized positive-item embeddings
__device__ float g_lse[B];      // per-row logsumexp(sim[i,:])
__device__ float g_pos[B];      // diagonal sim[i,i]

// ---------------------------------------------------------------------------
// Kernel 1: per-row L2 normalize of both matrices + diagonal similarity.
// One warp per batch row. D=256 -> 8 floats per lane, fully coalesced.
// ---------------------------------------------------------------------------
__global__ void __launch_bounds__(256) norm_pos_kernel(const float* __restrict__ u,
                                                       const float* __restrict__ p) {
    int warp = (blockIdx.x * blockDim.x + threadIdx.x) >> 5;
    int lane = threadIdx.x & 31;
    if (warp >= B) return;

    const float* ur = u + (size_t)warp * D;
    const float* pr = p + (size_t)warp * D;

    float uv[8], pv[8];
    float su = 0.f, sp = 0.f, dp = 0.f;
#pragma unroll
    for (int i = 0; i < 8; i++) {
        uv[i] = ur[lane + i * 32];
        pv[i] = pr[lane + i * 32];
        su = fmaf(uv[i], uv[i], su);
        sp = fmaf(pv[i], pv[i], sp);
        dp = fmaf(uv[i], pv[i], dp);
    }
#pragma unroll
    for (int o = 16; o; o >>= 1) {
        su += __shfl_xor_sync(0xffffffffu, su, o);
        sp += __shfl_xor_sync(0xffffffffu, sp, o);
        dp += __shfl_xor_sync(0xffffffffu, dp, o);
    }
    float iu = 1.0f / fmaxf(sqrtf(su), 1e-12f);
    float ip = 1.0f / fmaxf(sqrtf(sp), 1e-12f);

    float* uo = g_un + (size_t)warp * D;
    float* po = g_pn + (size_t)warp * D;
#pragma unroll
    for (int i = 0; i < 8; i++) {
        uo[lane + i * 32] = uv[i] * iu;
        po[lane + i * 32] = pv[i] * ip;
    }
    if (lane == 0) g_pos[warp] = dp * iu * ip * INV_T;
}

// ---------------------------------------------------------------------------
// Kernel 2: fused sim-GEMM + online logsumexp.
// Tile: BM=64 rows x BN=64 cols per CTA; 16x16 threads, 4x4 micro-tile.
// K tiled by BK=32 through shared memory ([BK][BM+1] transposed layout:
// conflict-free stores, broadcast/2-way reads).
// Each thread keeps running (max, sumexp) for its 4 rows across all N tiles;
// at the end the 16 lanes sharing a row merge via shfl (width 16).
// ---------------------------------------------------------------------------
#define BM 64
#define BN 64
#define BK 32

__global__ void __launch_bounds__(256) simlse_kernel() {
    __shared__ float uS[BK][BM + 1];
    __shared__ float pS[BK][BN + 1];

    const int tx = threadIdx.x & 15;       // col group
    const int ty = threadIdx.x >> 4;       // row group
    const int rowBase = blockIdx.x * BM;

    float m[4], s[4];
#pragma unroll
    for (int i = 0; i < 4; i++) { m[i] = -1e30f; s[i] = 0.f; }

    for (int nb = 0; nb < B; nb += BN) {
        float acc[4][4];
#pragma unroll
        for (int i = 0; i < 4; i++)
#pragma unroll
            for (int j = 0; j < 4; j++) acc[i][j] = 0.f;

        for (int kb = 0; kb < D; kb += BK) {
            // cooperative tile load: 2048 elems per tile, 8 per thread, coalesced
#pragma unroll
            for (int t = 0; t < 8; t++) {
                int e  = threadIdx.x + t * 256;
                int r  = e >> 5;        // 0..63
                int kk = e & 31;        // 0..31
                uS[kk][r] = g_un[(size_t)(rowBase + r) * D + kb + kk];
                pS[kk][r] = g_pn[(size_t)(nb + r) * D + kb + kk];
            }
            __syncthreads();

#pragma unroll
            for (int k = 0; k < BK; k++) {
                float a[4], b[4];
#pragma unroll
                for (int i = 0; i < 4; i++) a[i] = uS[k][ty * 4 + i];
#pragma unroll
                for (int j = 0; j < 4; j++) b[j] = pS[k][tx * 4 + j];
#pragma unroll
                for (int i = 0; i < 4; i++)
#pragma unroll
                    for (int j = 0; j < 4; j++)
                        acc[i][j] = fmaf(a[i], b[j], acc[i][j]);
            }
            __syncthreads();
        }

        // fold this 4x4 block of sim into the running row-wise LSE state
#pragma unroll
        for (int i = 0; i < 4; i++) {
            float v[4];
            float lm = -1e30f;
#pragma unroll
            for (int j = 0; j < 4; j++) {
                v[j] = acc[i][j] * INV_T;
                lm = fmaxf(lm, v[j]);
            }
            float nm  = fmaxf(m[i], lm);
            float add = 0.f;
#pragma unroll
            for (int j = 0; j < 4; j++) add += __expf(v[j] - nm);
            s[i] = fmaf(s[i], __expf(m[i] - nm), add);
            m[i] = nm;
        }
    }

    // merge (m, s) across the 16 lanes (tx) that share each row
#pragma unroll
    for (int i = 0; i < 4; i++) {
#pragma unroll
        for (int o = 8; o; o >>= 1) {
            float mo = __shfl_xor_sync(0xffffffffu, m[i], o, 16);
            float so = __shfl_xor_sync(0xffffffffu, s[i], o, 16);
            float nm = fmaxf(m[i], mo);
            s[i] = s[i] * __expf(m[i] - nm) + so * __expf(mo - nm);
            m[i] = nm;
        }
        if (tx == 0) g_lse[rowBase + ty * 4 + i] = m[i] + __logf(s[i]);
    }
}

// ---------------------------------------------------------------------------
// Kernel 3: mean(lse - pos) -> scalar
// ---------------------------------------------------------------------------
__global__ void __launch_bounds__(256) reduce_kernel(float* __restrict__ out) {
    __shared__ float sm[256];
    float acc = 0.f;
    for (int i = threadIdx.x; i < B; i += 256) acc += g_lse[i] - g_pos[i];
    sm[threadIdx.x] = acc;
    __syncthreads();
#pragma unroll
    for (int w = 128; w > 0; w >>= 1) {
        if (threadIdx.x < w) sm[threadIdx.x] += sm[threadIdx.x + w];
        __syncthreads();
    }
    if (threadIdx.x == 0) out[0] = sm[0] * (1.0f / (float)B);
}

// ---------------------------------------------------------------------------
extern "C" void kernel_launch(void* const* d_in, const int* in_sizes, int n_in,
                              void* d_out, int out_size) {
    const float* u = (const float*)d_in[0];
    const float* p = (const float*)d_in[1];
    float* out = (float*)d_out;

    // B rows, one warp per row, both matrices handled together
    norm_pos_kernel<<<(B * 32) / 256, 256>>>(u, p);
    simlse_kernel<<<B / BM, 256>>>();
    reduce_kernel<<<1, 256>>>(out);
}